// round 4
// baseline (speedup 1.0000x reference)
#include <cuda_runtime.h>

#define L      2048
#define BATCH  512
#define NDIM   128

#define TT 64   // t-tile
#define BB 64   // batch-tile
#define TS 64   // s-tile
#define US 65   // Us row stride (odd -> conflict-free)

// ---------------- scratch (__device__ globals, allocation-free) ----------------
__device__ double g_S[2][NDIM * NDIM];   // S_k = A^(2^k), row-major, ping-pong
__device__ double g_R[2][NDIM * NDIM];   // R_k = (A^64)^(2^k) TRANSPOSED, ping-pong
__device__ double g_W[64 * NDIM];        // w_j = (A^T)^j B
__device__ double g_Y[32 * NDIM];        // y_i = (A^64)^i C
__device__ float  g_h[L];                // h_k = B A^k C

// ---------------------------------------------------------------------------
__global__ void init_kernel(const float* __restrict__ A,
                            const float* __restrict__ B,
                            const float* __restrict__ C)
{
    int idx = blockIdx.x * blockDim.x + threadIdx.x;   // 64*256 = 16384
    if (idx < NDIM * NDIM) g_S[0][idx] = (double)A[idx];
    if (idx < NDIM) { g_W[idx] = (double)B[idx]; g_Y[idx] = (double)C[idx]; }
}

// High-MLP fp64 dot of a shared vector with a strided-global column.
// out = sum_k sh[k] * M[k*NDIM + c], fully unrolled, 16 loads in flight.
__device__ __forceinline__ double col_dot(const double* __restrict__ M,
                                          const double* sh, int c)
{
    double a0 = 0, a1 = 0, a2 = 0, a3 = 0;
#pragma unroll
    for (int kk = 0; kk < NDIM; kk += 16) {
        double s[16];
#pragma unroll
        for (int q = 0; q < 16; ++q) s[q] = M[(kk + q) * NDIM + c];
#pragma unroll
        for (int q = 0; q < 16; q += 4) {
            a0 += sh[kk + q + 0] * s[q + 0];
            a1 += sh[kk + q + 1] * s[q + 1];
            a2 += sh[kk + q + 2] * s[q + 2];
            a3 += sh[kk + q + 3] * s[q + 3];
        }
    }
    return (a0 + a1) + (a2 + a3);
}

// Stage k of W phase (k=0..5), grid = 128 + 2^k blocks of 128 threads:
//   blocks [0,128): squaring  S_{k+1} = S_k * S_k  (k==5: write transposed -> R_0)
//   blocks [128,..): expand   w_{2^k + j} = (A^T)^{2^k} w_j
__global__ __launch_bounds__(128) void stageW_kernel(int k, int cur)
{
    __shared__ double sh[NDIM];
    const double* __restrict__ S = g_S[cur];
    if (blockIdx.x < 128) {                    // ---- squaring ----
        const int r = blockIdx.x, c = threadIdx.x;
        sh[c] = S[r * NDIM + c];
        __syncthreads();
        double acc = col_dot(S, sh, c);
        if (k == 5) g_R[0][c * NDIM + r] = acc;          // R_0 = (A^64)^T
        else        g_S[cur ^ 1][r * NDIM + c] = acc;
    } else {                                   // ---- expand W ----
        const int j = blockIdx.x - 128;
        const int i = threadIdx.x;
        const int m = 1 << k;
        sh[i] = g_W[j * NDIM + i];
        __syncthreads();
        // (A^T)^m [i][c] = S_k[c][i]  -> column-dot with coalesced loads
        g_W[(m + j) * NDIM + i] = col_dot(S, sh, i);
    }
}

// Stage k of Y phase (k=0..4):
//   k<4 : grid = 128 + 2^k ; blocks [0,128) square R, rest expand Y
//   k==4: grid = 16 ; all blocks expand
__global__ __launch_bounds__(128) void stageY_kernel(int k, int cur)
{
    __shared__ double sh[NDIM];
    const double* __restrict__ R = g_R[cur];
    if (k < 4 && blockIdx.x < 128) {           // ---- squaring (transposed space) ----
        const int r = blockIdx.x, c = threadIdx.x;
        sh[c] = R[r * NDIM + c];
        __syncthreads();
        g_R[cur ^ 1][r * NDIM + c] = col_dot(R, sh, c);
    } else {                                   // ---- expand Y ----
        const int j = (k < 4) ? (int)blockIdx.x - 128 : (int)blockIdx.x;
        const int i = threadIdx.x;
        const int m = 1 << k;
        sh[i] = g_Y[j * NDIM + i];
        __syncthreads();
        // M^m [i][c] = R_k[c][i]
        g_Y[(m + j) * NDIM + i] = col_dot(R, sh, i);
    }
}

// h[64*i + j] = w_j . y_i   (block = i, 256 threads, 4 lanes per dot)
__global__ void hdot_kernel()
{
    __shared__ double ys[NDIM];
    const int i = blockIdx.x;
    const int tid = threadIdx.x;
    if (tid < NDIM) ys[tid] = g_Y[i * NDIM + tid];
    __syncthreads();
    const int j = tid >> 2, q = tid & 3;
    const double* __restrict__ w = &g_W[j * NDIM + q * 32];
    const double* __restrict__ y = &ys[q * 32];
    double p = 0;
#pragma unroll
    for (int c = 0; c < 32; ++c) p += w[c] * y[c];
    p += __shfl_xor_sync(0xFFFFFFFFu, p, 1);
    p += __shfl_xor_sync(0xFFFFFFFFu, p, 2);
    if (q == 0) g_h[i * 64 + j] = (float)p;
}

// ---------------------------------------------------------------------------
// Causal Toeplitz conv: out[b,t] = f_t * sum_{s<=t} h[t-s] u[b,s] + D u[b,t]
// 128 threads/block, 8t x 4b per thread, Us[ss][65] conflict-free layout,
// heaviest tiles scheduled first.
// ---------------------------------------------------------------------------
__global__ __launch_bounds__(128) void conv_kernel(const float* __restrict__ u,
                                                   const float* __restrict__ Dp,
                                                   float* __restrict__ out)
{
    __shared__ float Us[TS][US];        // [ss][bb], stride 65
    __shared__ float hsArr[132];
    float* hsp = hsArr + 4;

    const int z     = blockIdx.x;
    const int tileT = 31 - (z >> 3);        // heaviest (tileT=31) first
    const int t0    = tileT * TT;
    const int b0    = (z & 7) * BB;
    const int tid   = threadIdx.x;
    const int tx    = tid & 7;              // 8 t-groups
    const int ty    = tid >> 3;             // 16 b-groups
    const int tt0   = tx * 8;
    const int bb0   = ty * 4;

    float acc[8][4];
#pragma unroll
    for (int r = 0; r < 8; ++r)
#pragma unroll
        for (int q = 0; q < 4; ++q) acc[r][q] = 0.0f;

    if (tid < 4) hsArr[tid] = 0.0f;         // guards hsp[-4..-1]

    for (int st = 0; st <= tileT; ++st) {
        const int s0 = st * TS;
        __syncthreads();
        // h window: hsp[d] = h[t0-s0-63+d], zero OOB
        {
            int g = t0 - s0 - 63 + tid;
            hsp[tid] = (g >= 0 && g < L) ? g_h[g] : 0.0f;
        }
        // u tile: coalesced LDG.32, conflict-free STS (ss across warp, stride 65)
#pragma unroll
        for (int p = 0; p < 32; ++p) {
            int f  = p * 128 + tid;
            int bb = f >> 6;
            int ss = f & 63;
            Us[ss][bb] = u[(size_t)(b0 + bb) * L + (s0 + ss)];
        }
        __syncthreads();

        float w[8];
#pragma unroll
        for (int r = 0; r < 8; ++r) w[r] = hsp[tt0 + 63 + r];

#pragma unroll 8
        for (int ss = 0; ss < TS; ++ss) {
            float u0 = Us[ss][bb0 + 0];
            float u1 = Us[ss][bb0 + 1];
            float u2 = Us[ss][bb0 + 2];
            float u3 = Us[ss][bb0 + 3];
#pragma unroll
            for (int r = 0; r < 8; ++r) {
                acc[r][0] += w[r] * u0;
                acc[r][1] += w[r] * u1;
                acc[r][2] += w[r] * u2;
                acc[r][3] += w[r] * u3;
            }
            float nw = hsp[tt0 + 62 - ss];   // hsp[-1] is zeroed guard
#pragma unroll
            for (int r = 7; r > 0; --r) w[r] = w[r - 1];
            w[0] = nw;
        }
    }

    const float Dv = Dp[0];
#pragma unroll
    for (int r = 0; r < 8; ++r) {
        const int t = t0 + tt0 + r;
        const float f = (t == 0) ? 1.0f : 2.0f;
#pragma unroll
        for (int q = 0; q < 4; ++q) {
            const size_t off = (size_t)(b0 + bb0 + q) * L + t;
            out[off] = f * acc[r][q] + Dv * u[off];
        }
    }
}

// ---------------------------------------------------------------------------
extern "C" void kernel_launch(void* const* d_in, const int* in_sizes, int n_in,
                              void* d_out, int out_size)
{
    const float* u  = (const float*)d_in[0];  // (512, 2048)
    const float* A  = (const float*)d_in[1];  // (128, 128)
    const float* B  = (const float*)d_in[2];  // (128,)
    const float* Cd = (const float*)d_in[3];  // (128,)
    const float* Dd = (const float*)d_in[4];  // (1,)
    float* out = (float*)d_out;               // (512, 2048)

    init_kernel<<<64, 256>>>(A, B, Cd);

    int cs = 0;
    for (int k = 0; k <= 5; ++k) {
        stageW_kernel<<<128 + (1 << k), 128>>>(k, cs);
        if (k < 5) cs ^= 1;
    }
    int cr = 0;
    for (int k = 0; k <= 4; ++k) {
        int grid = (k < 4) ? 128 + (1 << k) : (1 << k);
        stageY_kernel<<<grid, 128>>>(k, cr);
        if (k < 4) cr ^= 1;
    }
    hdot_kernel<<<32, 256>>>();

    conv_kernel<<<256, 128>>>(u, Dd, out);
}

// round 5
// speedup vs baseline: 1.3986x; 1.3986x over previous
#include <cuda_runtime.h>

#define L      2048
#define BATCH  512
#define NDIM   128

#define TT 64
#define BB 64
#define TS 64
#define US 66   // even stride -> 8B-aligned rows for LDS.64
#define CH 32   // k-chunk rows staged in smem

typedef unsigned long long u64;

// ---------------- scratch (__device__ globals, allocation-free) ----------------
__device__ __align__(16) double g_S[2][NDIM * NDIM];  // A^(2^k) chain, ping-pong
__device__ __align__(16) double g_R[2][NDIM * NDIM];  // (A^(64*2^k))^T chain
__device__ __align__(16) double g_W[64 * NDIM];       // w_j = (A^T)^j B
__device__ __align__(16) double g_Y[32 * NDIM];       // y_i = A^(64 i) C
__device__ float  g_h[L];                             // h_n = B A^n C

// ---------------------------------------------------------------------------
// Block-cooperative column dot: acc = sum_k sh[k] * M[k*NDIM + tid].
// Matrix streamed through smem in CH-row chunks; chunk loads are independent
// & coalesced (structural MLP), accumulation reads smem (29-cyc latency).
// If Af != nullptr, the matrix is the fp32 input A (converted on load).
// ---------------------------------------------------------------------------
__device__ __forceinline__ double staged_col_dot(const double* __restrict__ Mg,
                                                 const float* __restrict__ Af,
                                                 const double* sh,
                                                 double* tile, int tid)
{
    double a0 = 0, a1 = 0, a2 = 0, a3 = 0;
    for (int kk = 0; kk < NDIM; kk += CH) {
        __syncthreads();                       // tile reuse barrier
        if (Af) {
            const float* src = Af + kk * NDIM;
#pragma unroll
            for (int q = 0; q < CH; ++q)
                tile[q * NDIM + tid] = (double)src[q * NDIM + tid];
        } else {
            const double2* src = (const double2*)(Mg + kk * NDIM);
            double2* dst = (double2*)tile;
#pragma unroll
            for (int p = 0; p < (CH * NDIM / 2) / 128; ++p)   // 16 indep double2
                dst[p * 128 + tid] = src[p * 128 + tid];
        }
        __syncthreads();
#pragma unroll
        for (int q = 0; q < CH; q += 4) {
            a0 += sh[kk + q + 0] * tile[(q + 0) * NDIM + tid];
            a1 += sh[kk + q + 1] * tile[(q + 1) * NDIM + tid];
            a2 += sh[kk + q + 2] * tile[(q + 2) * NDIM + tid];
            a3 += sh[kk + q + 3] * tile[(q + 3) * NDIM + tid];
        }
    }
    return (a0 + a1) + (a2 + a3);
}

// Stage k of W phase (k=0..5). grid = (k==0 ? 130 : 128 + 2^k), 128 threads.
//   blocks [0,128): squaring  S_{k+1} = S_k S_k   (k==5: write transposed -> R_0)
//   blocks [128, 128+2^k): expand w_{2^k+j} = (A^T)^{2^k} w_j
//   block 129 (k==0 only): y_0 = C
// k==0 reads the fp32 input A directly (init fused).
__global__ __launch_bounds__(128) void stageW_kernel(int k,
                                                     const float* __restrict__ Af,
                                                     const float* __restrict__ Bf,
                                                     const float* __restrict__ Cf)
{
    __shared__ double sh[NDIM];
    __shared__ __align__(16) double tile[CH * NDIM];
    const int tid = threadIdx.x;
    const double* S = g_S[k & 1];              // valid for k>=1
    const float* Au = (k == 0) ? Af : nullptr;

    if (blockIdx.x < 128) {                    // ---- squaring ----
        const int r = blockIdx.x;
        sh[tid] = (k == 0) ? (double)Af[r * NDIM + tid] : S[r * NDIM + tid];
        double acc = staged_col_dot(S, Au, sh, tile, tid);
        if (k == 5) g_R[0][tid * NDIM + r] = acc;          // R_0 = (A^64)^T
        else        g_S[(k + 1) & 1][r * NDIM + tid] = acc;
    } else if ((int)blockIdx.x < 128 + (1 << k)) {         // ---- expand W ----
        const int j = blockIdx.x - 128;
        const int m = 1 << k;
        if (k == 0) { double b = (double)Bf[tid]; g_W[tid] = b; sh[tid] = b; }
        else        sh[tid] = g_W[j * NDIM + tid];
        double acc = staged_col_dot(S, Au, sh, tile, tid);
        g_W[(m + j) * NDIM + tid] = acc;
    } else {                                   // ---- y_0 = C (k==0 only) ----
        g_Y[tid] = (double)Cf[tid];
    }
}

// Stage k of Y phase (k=0..4). k<4: grid = 128 + 2^k (square + expand);
// k==4: grid = 16 (expand only). All in transposed (R) space.
__global__ __launch_bounds__(128) void stageY_kernel(int k)
{
    __shared__ double sh[NDIM];
    __shared__ __align__(16) double tile[CH * NDIM];
    const int tid = threadIdx.x;
    const double* R = g_R[k & 1];

    if (k < 4 && blockIdx.x < 128) {           // ---- squaring ----
        const int r = blockIdx.x;
        sh[tid] = R[r * NDIM + tid];
        g_R[(k + 1) & 1][r * NDIM + tid] = staged_col_dot(R, nullptr, sh, tile, tid);
    } else {                                   // ---- expand Y ----
        const int j = (k < 4) ? (int)blockIdx.x - 128 : (int)blockIdx.x;
        const int m = 1 << k;
        sh[tid] = g_Y[j * NDIM + tid];
        g_Y[(m + j) * NDIM + tid] = staged_col_dot(R, nullptr, sh, tile, tid);
    }
}

// h[64*i + j] = w_j . y_i   (block = i, 256 threads, 4 lanes per dot)
__global__ void hdot_kernel()
{
    __shared__ double ys[NDIM];
    const int i = blockIdx.x;
    const int tid = threadIdx.x;
    if (tid < NDIM) ys[tid] = g_Y[i * NDIM + tid];
    __syncthreads();
    const int j = tid >> 2, q = tid & 3;
    const double* __restrict__ w = &g_W[j * NDIM + q * 32];
    const double* __restrict__ y = &ys[q * 32];
    double p = 0;
#pragma unroll
    for (int c = 0; c < 32; ++c) p += w[c] * y[c];
    p += __shfl_xor_sync(0xFFFFFFFFu, p, 1);
    p += __shfl_xor_sync(0xFFFFFFFFu, p, 2);
    if (q == 0) g_h[i * 64 + j] = (float)p;
}

// ---------------------------------------------------------------------------
// Packed f32x2 helpers (Blackwell sm_100a; exact fp32 FMA semantics)
// ---------------------------------------------------------------------------
__device__ __forceinline__ void ffma2(u64& d, u64 a, u64 b)
{
    asm("fma.rn.f32x2 %0, %1, %2, %0;" : "+l"(d) : "l"(a), "l"(b));
}
__device__ __forceinline__ u64 splat2(float x)
{
    u64 r; asm("mov.b64 %0, {%1, %1};" : "=l"(r) : "f"(x)); return r;
}
__device__ __forceinline__ void unpack2(u64 v, float& lo, float& hi)
{
    asm("mov.b64 {%0, %1}, %2;" : "=f"(lo), "=f"(hi) : "l"(v));
}

// ---------------------------------------------------------------------------
// Causal Toeplitz conv: out[b,t] = f_t * sum_{s<=t} h[t-s] u[b,s] + D u[b,t]
// 128 thr/block, 8t x 4b per thread (batches packed in pairs -> FFMA2),
// heaviest tiles scheduled first.
// ---------------------------------------------------------------------------
__global__ __launch_bounds__(128) void conv_kernel(const float* __restrict__ u,
                                                   const float* __restrict__ Dp,
                                                   float* __restrict__ out)
{
    __shared__ __align__(16) float Us[TS][US];   // [ss][bb]
    __shared__ float hsArr[132];
    float* hsp = hsArr + 4;

    const int z     = blockIdx.x;
    const int tileT = 31 - (z >> 3);        // heaviest first
    const int t0    = tileT * TT;
    const int b0    = (z & 7) * BB;
    const int tid   = threadIdx.x;
    const int tx    = tid & 7;
    const int ty    = tid >> 3;
    const int tt0   = tx * 8;
    const int bb0   = ty * 4;

    u64 acc2[8][2];
#pragma unroll
    for (int r = 0; r < 8; ++r) { acc2[r][0] = 0ull; acc2[r][1] = 0ull; }

    if (tid < 4) hsArr[tid] = 0.0f;         // guards hsp[-4..-1]

    for (int st = 0; st <= tileT; ++st) {
        const int s0 = st * TS;
        __syncthreads();
        {   // h window: hsp[d] = h[t0-s0-63+d], zero OOB
            int g = t0 - s0 - 63 + tid;
            hsp[tid] = (g >= 0 && g < L) ? g_h[g] : 0.0f;
        }
#pragma unroll
        for (int p = 0; p < 32; ++p) {      // coalesced LDG fill
            int f  = p * 128 + tid;
            int bb = f >> 6;
            int ss = f & 63;
            Us[ss][bb] = u[(size_t)(b0 + bb) * L + (s0 + ss)];
        }
        __syncthreads();

        u64 w2[8];
#pragma unroll
        for (int r = 0; r < 8; ++r) w2[r] = splat2(hsp[tt0 + 63 + r]);

#pragma unroll 8
        for (int ss = 0; ss < TS; ++ss) {
            u64 u01 = *(const u64*)&Us[ss][bb0];
            u64 u23 = *(const u64*)&Us[ss][bb0 + 2];
#pragma unroll
            for (int r = 0; r < 8; ++r) {
                ffma2(acc2[r][0], u01, w2[r]);
                ffma2(acc2[r][1], u23, w2[r]);
            }
            float nw = hsp[tt0 + 62 - ss];  // hsp[-1] is zeroed guard
#pragma unroll
            for (int r = 7; r > 0; --r) w2[r] = w2[r - 1];
            w2[0] = splat2(nw);
        }
    }

    const float Dv = Dp[0];
#pragma unroll
    for (int r = 0; r < 8; ++r) {
        const int t = t0 + tt0 + r;
        const float f = (t == 0) ? 1.0f : 2.0f;
#pragma unroll
        for (int p = 0; p < 2; ++p) {
            float lo, hi;
            unpack2(acc2[r][p], lo, hi);
            const int b = b0 + bb0 + 2 * p;
            const size_t o0 = (size_t)b * L + t;
            const size_t o1 = (size_t)(b + 1) * L + t;
            out[o0] = f * lo + Dv * u[o0];
            out[o1] = f * hi + Dv * u[o1];
        }
    }
}

// ---------------------------------------------------------------------------
extern "C" void kernel_launch(void* const* d_in, const int* in_sizes, int n_in,
                              void* d_out, int out_size)
{
    const float* u  = (const float*)d_in[0];  // (512, 2048)
    const float* A  = (const float*)d_in[1];  // (128, 128)
    const float* B  = (const float*)d_in[2];  // (128,)
    const float* Cd = (const float*)d_in[3];  // (128,)
    const float* Dd = (const float*)d_in[4];  // (1,)
    float* out = (float*)d_out;               // (512, 2048)

    for (int k = 0; k <= 5; ++k) {
        int grid = (k == 0) ? 130 : 128 + (1 << k);
        stageW_kernel<<<grid, 128>>>(k, A, B, Cd);
    }
    for (int k = 0; k <= 4; ++k) {
        int grid = (k < 4) ? 128 + (1 << k) : 16;
        stageY_kernel<<<grid, 128>>>(k);
    }
    hdot_kernel<<<32, 256>>>();

    conv_kernel<<<256, 128>>>(u, Dd, out);
}

// round 6
// speedup vs baseline: 1.7525x; 1.2531x over previous
#include <cuda_runtime.h>

#define L      2048
#define BATCH  512
#define NDIM   128

#define TT 64
#define BB 64
#define TS 64
#define US 66   // even stride -> 8B-aligned rows for LDS.64, conflict-free reads
#define CH 64   // k-chunk rows staged in smem (64 rows * 128 f32 = 32 KB)

typedef unsigned long long u64;

// ---------------- scratch (__device__ globals, allocation-free) ----------------
__device__ __align__(16) float g_S[2][NDIM * NDIM];  // A^(2^k) chain, ping-pong
__device__ __align__(16) float g_R[2][NDIM * NDIM];  // (A^(64*2^k))^T chain
__device__ __align__(16) float g_W[64 * NDIM];       // w_j = (A^T)^j B
__device__ __align__(16) float g_Y[32 * NDIM];       // y_i = A^(64 i) C
__device__ float g_h[L];                             // h_n = B A^n C

// ---------------------------------------------------------------------------
// Block-cooperative fp32 column dot: acc = sum_k sh[k] * M[k*NDIM + tid].
// Matrix streamed through smem in CH-row chunks via independent float4 loads;
// accumulation is FFMA-bound (fast) instead of DFMA-bound.
// ---------------------------------------------------------------------------
__device__ __forceinline__ float staged_col_dot(const float* __restrict__ M,
                                                const float* sh,
                                                float* tile, int tid)
{
    float a0 = 0.f, a1 = 0.f, a2 = 0.f, a3 = 0.f;
#pragma unroll
    for (int kk = 0; kk < NDIM; kk += CH) {
        __syncthreads();                       // tile reuse barrier
        const float4* src = (const float4*)(M + kk * NDIM);
        float4* dst = (float4*)tile;
#pragma unroll
        for (int p = 0; p < (CH * NDIM / 4) / 128; ++p)   // 16 indep float4
            dst[p * 128 + tid] = src[p * 128 + tid];
        __syncthreads();
#pragma unroll
        for (int q = 0; q < CH; q += 4) {
            a0 += sh[kk + q + 0] * tile[(q + 0) * NDIM + tid];
            a1 += sh[kk + q + 1] * tile[(q + 1) * NDIM + tid];
            a2 += sh[kk + q + 2] * tile[(q + 2) * NDIM + tid];
            a3 += sh[kk + q + 3] * tile[(q + 3) * NDIM + tid];
        }
    }
    return (a0 + a1) + (a2 + a3);
}

// Stage k of W phase (k=0..5). grid = (k==0 ? 130 : 128 + 2^k), 128 threads.
//   blocks [0,128): squaring  S_{k+1} = S_k S_k   (k==5: write transposed -> R_0)
//   blocks [128, 128+2^k): expand w_{2^k+j} = (A^T)^{2^k} w_j
//   block 129 (k==0 only): y_0 = C
// k==0 reads the fp32 input A directly (init fused).
__global__ __launch_bounds__(128) void stageW_kernel(int k,
                                                     const float* __restrict__ Af,
                                                     const float* __restrict__ Bf,
                                                     const float* __restrict__ Cf)
{
    __shared__ float sh[NDIM];
    __shared__ __align__(16) float tile[CH * NDIM];
    const int tid = threadIdx.x;
    const float* M = (k == 0) ? Af : g_S[k & 1];

    if (blockIdx.x < 128) {                    // ---- squaring ----
        const int r = blockIdx.x;
        sh[tid] = M[r * NDIM + tid];
        float acc = staged_col_dot(M, sh, tile, tid);
        if (k == 5) g_R[0][tid * NDIM + r] = acc;          // R_0 = (A^64)^T
        else        g_S[(k + 1) & 1][r * NDIM + tid] = acc;
    } else if ((int)blockIdx.x < 128 + (1 << k)) {         // ---- expand W ----
        const int j = blockIdx.x - 128;
        const int m = 1 << k;
        if (k == 0) { float b = Bf[tid]; g_W[tid] = b; sh[tid] = b; }
        else        sh[tid] = g_W[j * NDIM + tid];
        float acc = staged_col_dot(M, sh, tile, tid);
        g_W[(m + j) * NDIM + tid] = acc;
    } else {                                   // ---- y_0 = C (k==0 only) ----
        g_Y[tid] = Cf[tid];
    }
}

// Stage k of Y phase (k=0..4). k<4: grid = 128 + 2^k (square + expand);
// k==4: grid = 16 (expand only). All in transposed (R) space.
__global__ __launch_bounds__(128) void stageY_kernel(int k)
{
    __shared__ float sh[NDIM];
    __shared__ __align__(16) float tile[CH * NDIM];
    const int tid = threadIdx.x;
    const float* R = g_R[k & 1];

    if (k < 4 && blockIdx.x < 128) {           // ---- squaring ----
        const int r = blockIdx.x;
        sh[tid] = R[r * NDIM + tid];
        g_R[(k + 1) & 1][r * NDIM + tid] = staged_col_dot(R, sh, tile, tid);
    } else {                                   // ---- expand Y ----
        const int j = (k < 4) ? (int)blockIdx.x - 128 : (int)blockIdx.x;
        const int m = 1 << k;
        sh[tid] = g_Y[j * NDIM + tid];
        g_Y[(m + j) * NDIM + tid] = staged_col_dot(R, sh, tile, tid);
    }
}

// h[64*i + j] = w_j . y_i   (block = i, 256 threads, 4 lanes per dot)
__global__ void hdot_kernel()
{
    __shared__ float ys[NDIM];
    const int i = blockIdx.x;
    const int tid = threadIdx.x;
    if (tid < NDIM) ys[tid] = g_Y[i * NDIM + tid];
    __syncthreads();
    const int j = tid >> 2, q = tid & 3;
    const float* __restrict__ w = &g_W[j * NDIM + q * 32];
    const float* __restrict__ y = &ys[q * 32];
    float p0 = 0.f, p1 = 0.f;
#pragma unroll
    for (int c = 0; c < 32; c += 2) { p0 += w[c] * y[c]; p1 += w[c + 1] * y[c + 1]; }
    float p = p0 + p1;
    p += __shfl_xor_sync(0xFFFFFFFFu, p, 1);
    p += __shfl_xor_sync(0xFFFFFFFFu, p, 2);
    if (q == 0) g_h[i * 64 + j] = p;
}

// ---------------------------------------------------------------------------
// Packed f32x2 helpers (Blackwell sm_100a; exact fp32 FMA semantics)
// ---------------------------------------------------------------------------
__device__ __forceinline__ void ffma2(u64& d, u64 a, u64 b)
{
    asm("fma.rn.f32x2 %0, %1, %2, %0;" : "+l"(d) : "l"(a), "l"(b));
}
__device__ __forceinline__ u64 splat2(float x)
{
    u64 r; asm("mov.b64 %0, {%1, %1};" : "=l"(r) : "f"(x)); return r;
}
__device__ __forceinline__ void unpack2(u64 v, float& lo, float& hi)
{
    asm("mov.b64 {%0, %1}, %2;" : "=f"(lo), "=f"(hi) : "l"(v));
}

// ---------------------------------------------------------------------------
// Causal Toeplitz conv: out[b,t] = f_t * sum_{s<=t} h[t-s] u[b,s] + D u[b,t]
// 128 thr/block, 8t x 4b per thread (batch pairs packed -> FFMA2),
// inner 64-loop FULLY unrolled so the h-window rotation is register-renamed.
// ---------------------------------------------------------------------------
__global__ __launch_bounds__(128) void conv_kernel(const float* __restrict__ u,
                                                   const float* __restrict__ Dp,
                                                   float* __restrict__ out)
{
    __shared__ __align__(16) float Us[TS][US];   // [ss][bb]
    __shared__ float hsArr[132];
    float* hsp = hsArr + 4;

    const int z     = blockIdx.x;
    const int tileT = 31 - (z >> 3);        // heaviest first
    const int t0    = tileT * TT;
    const int b0    = (z & 7) * BB;
    const int tid   = threadIdx.x;
    const int tx    = tid & 7;
    const int ty    = tid >> 3;
    const int tt0   = tx * 8;
    const int bb0   = ty * 4;

    u64 acc2[8][2];
#pragma unroll
    for (int r = 0; r < 8; ++r) { acc2[r][0] = 0ull; acc2[r][1] = 0ull; }

    if (tid < 4) hsArr[tid] = 0.0f;         // guards hsp[-4..-1]

    for (int st = 0; st <= tileT; ++st) {
        const int s0 = st * TS;
        __syncthreads();
        {   // h window: hsp[d] = h[t0-s0-63+d], zero OOB
            int g = t0 - s0 - 63 + tid;
            hsp[tid] = (g >= 0 && g < L) ? g_h[g] : 0.0f;
        }
#pragma unroll
        for (int p = 0; p < 32; ++p) {      // coalesced LDG fill
            int f  = p * 128 + tid;
            int bb = f >> 6;
            int ss = f & 63;
            Us[ss][bb] = u[(size_t)(b0 + bb) * L + (s0 + ss)];
        }
        __syncthreads();

        u64 w2[8];
#pragma unroll
        for (int r = 0; r < 8; ++r) w2[r] = splat2(hsp[tt0 + 63 + r]);

#pragma unroll
        for (int ss = 0; ss < TS; ++ss) {
            u64 u01 = *(const u64*)&Us[ss][bb0];
            u64 u23 = *(const u64*)&Us[ss][bb0 + 2];
#pragma unroll
            for (int r = 0; r < 8; ++r) {
                ffma2(acc2[r][0], u01, w2[r]);
                ffma2(acc2[r][1], u23, w2[r]);
            }
            float nw = hsp[tt0 + 62 - ss];  // hsp[-1] is zeroed guard
#pragma unroll
            for (int r = 7; r > 0; --r) w2[r] = w2[r - 1];
            w2[0] = splat2(nw);
        }
    }

    const float Dv = Dp[0];
#pragma unroll
    for (int r = 0; r < 8; ++r) {
        const int t = t0 + tt0 + r;
        const float f = (t == 0) ? 1.0f : 2.0f;
#pragma unroll
        for (int p = 0; p < 2; ++p) {
            float lo, hi;
            unpack2(acc2[r][p], lo, hi);
            const int b = b0 + bb0 + 2 * p;
            const size_t o0 = (size_t)b * L + t;
            const size_t o1 = (size_t)(b + 1) * L + t;
            out[o0] = f * lo + Dv * u[o0];
            out[o1] = f * hi + Dv * u[o1];
        }
    }
}

// ---------------------------------------------------------------------------
extern "C" void kernel_launch(void* const* d_in, const int* in_sizes, int n_in,
                              void* d_out, int out_size)
{
    const float* u  = (const float*)d_in[0];  // (512, 2048)
    const float* A  = (const float*)d_in[1];  // (128, 128)
    const float* B  = (const float*)d_in[2];  // (128,)
    const float* Cd = (const float*)d_in[3];  // (128,)
    const float* Dd = (const float*)d_in[4];  // (1,)
    float* out = (float*)d_out;               // (512, 2048)

    for (int k = 0; k <= 5; ++k) {
        int grid = (k == 0) ? 130 : 128 + (1 << k);
        stageW_kernel<<<grid, 128>>>(k, A, B, Cd);
    }
    for (int k = 0; k <= 4; ++k) {
        int grid = (k < 4) ? 128 + (1 << k) : 16;
        stageY_kernel<<<grid, 128>>>(k);
    }
    hdot_kernel<<<32, 256>>>();

    conv_kernel<<<256, 128>>>(u, Dd, out);
}